// round 3
// baseline (speedup 1.0000x reference)
#include <cuda_runtime.h>

#define NPTS 6912
#define CF 16
#define BB 2
#define TILE 128
#define NT (NPTS / TILE)     /* 54 */
#define PREPB (NPTS / 256)   /* 27 */
#define EPSF 1e-8f
/* exp(-sq/0.1) = 2^(NEG_SCALE * sq) */
#define NEG_SCALE (-14.426950408889634f)
#define POS2SCALE (28.853900817779268f)

typedef unsigned long long u64;

/* ------------------------- device scratch ------------------------------- */
__device__ float  g_f1d[BB][CF][2 * NPTS];  /* f1 normalized, duplicated (v,v) */
__device__ float  g_f2n[BB][CF][NPTS];      /* f2 normalized */
__device__ float  g_x1d[BB][4][2 * NPTS];   /* rows 0-2: POS2SCALE*x1 dup; row 3: as dup */
__device__ float  g_xt [BB][3][NPTS];       /* xyz2 transformed */
__device__ float  g_xn [BB][3][NPTS];       /* xyz2 noisy */
__device__ float  g_bts[BB][NPTS];          /* NEG_SCALE*||xt||^2 */
__device__ float  g_bns[BB][NPTS];          /* NEG_SCALE*||xn||^2 */
__device__ float  g_part[BB][PREPB][3];     /* per-block: fns, sum m1, sum m2 */
__device__ double g_S[BB];

/* ------------------------- packed f32x2 helpers ------------------------- */
__device__ __forceinline__ float2 unpk(u64 v) {
    float2 r; asm("mov.b64 {%0, %1}, %2;" : "=f"(r.x), "=f"(r.y) : "l"(v)); return r;
}
__device__ __forceinline__ void fma2(u64 &d, u64 a, u64 b) {
    asm("fma.rn.f32x2 %0, %1, %2, %0;" : "+l"(d) : "l"(a), "l"(b));
}
__device__ __forceinline__ u64 add2(u64 a, u64 b) {
    u64 r; asm("add.rn.f32x2 %0, %1, %2;" : "=l"(r) : "l"(a), "l"(b)); return r;
}
__device__ __forceinline__ float fexp2(float x) {
    float r; asm("ex2.approx.f32 %0, %1;" : "=f"(r) : "f"(x)); return r;
}

/* ------------------------- prep: per-point quantities ------------------- */
__global__ void prep_kernel(const float* __restrict__ f1, const float* __restrict__ f2,
                            const float* __restrict__ dp1, const float* __restrict__ dp2,
                            const float* __restrict__ pose, const float* __restrict__ yz1) {
    const int b = blockIdx.y;
    const int i = blockIdx.x * blockDim.x + threadIdx.x;
    float fns, m1c, m2c;
    {
        float d1 = dp1[b * NPTS + i], d2 = dp2[b * NPTS + i];
        float m1 = (d1 > 0.f) ? 1.f : 0.f;
        float m2 = (d2 > 0.f) ? 1.f : 0.f;
        float v1[CF], v2[CF];
        float s1 = 0.f, s2 = 0.f;
#pragma unroll
        for (int c = 0; c < CF; c++) {
            v1[c] = f1[((size_t)b * CF + c) * NPTS + i];
            v2[c] = f2[((size_t)b * CF + c) * NPTS + i];
            s1 = fmaf(v1[c], v1[c], s1);
            s2 = fmaf(v2[c], v2[c], s2);
        }
        float n1 = sqrtf(s1), n2 = sqrtf(s2);
        float iv1 = m1 / (n1 + EPSF), iv2 = m2 / (n2 + EPSF);
#pragma unroll
        for (int c = 0; c < CF; c++) {
            float a = v1[c] * iv1;
            g_f1d[b][c][2 * i]     = a;
            g_f1d[b][c][2 * i + 1] = a;
            g_f2n[b][c][i] = v2[c] * iv2;
        }
        float y0 = yz1[i], y1 = yz1[NPTS + i], y2 = yz1[2 * NPTS + i];
        float ax = y0 * d1, ay = y1 * d1, az = y2 * d1;
        float as = NEG_SCALE * (ax * ax + ay * ay + az * az);
        g_x1d[b][0][2 * i] = g_x1d[b][0][2 * i + 1] = POS2SCALE * ax;
        g_x1d[b][1][2 * i] = g_x1d[b][1][2 * i + 1] = POS2SCALE * ay;
        g_x1d[b][2][2 * i] = g_x1d[b][2][2 * i + 1] = POS2SCALE * az;
        g_x1d[b][3][2 * i] = g_x1d[b][3][2 * i + 1] = as;
        float bx = y0 * d2, by = y1 * d2, bz = y2 * d2;
        g_xn[b][0][i] = bx; g_xn[b][1][i] = by; g_xn[b][2][i] = bz;
        g_bns[b][i] = NEG_SCALE * (bx * bx + by * by + bz * bz);
        const float* P = pose + b * 16;
        float tx = P[0] * bx + P[1] * by + P[2]  * bz + P[3];
        float ty = P[4] * bx + P[5] * by + P[6]  * bz + P[7];
        float tz = P[8] * bx + P[9] * by + P[10] * bz + P[11];
        g_xt[b][0][i] = tx; g_xt[b][1][i] = ty; g_xt[b][2][i] = tz;
        g_bts[b][i] = NEG_SCALE * (tx * tx + ty * ty + tz * tz);
        fns = n1 * m1 + n2 * m2; m1c = m1; m2c = m2;
    }
#pragma unroll
    for (int o = 16; o; o >>= 1) {
        fns += __shfl_down_sync(0xffffffffu, fns, o);
        m1c += __shfl_down_sync(0xffffffffu, m1c, o);
        m2c += __shfl_down_sync(0xffffffffu, m2c, o);
    }
    __shared__ float rf[8], r1[8], r2[8];
    int w = threadIdx.x >> 5, l = threadIdx.x & 31;
    if (l == 0) { rf[w] = fns; r1[w] = m1c; r2[w] = m2c; }
    __syncthreads();
    if (threadIdx.x == 0) {
        float a = 0.f, c1 = 0.f, c2 = 0.f;
#pragma unroll
        for (int k = 0; k < 8; k++) { a += rf[k]; c1 += r1[k]; c2 += r2[k]; }
        g_part[b][blockIdx.x][0] = a;
        g_part[b][blockIdx.x][1] = c1;
        g_part[b][blockIdx.x][2] = c2;
        if (blockIdx.x == 0) g_S[b] = 0.0;   /* zero before pair_kernel runs */
    }
}

/* ------------------------- main: 128x128 pair tiles --------------------- */
__global__ __launch_bounds__(512, 1) void pair_kernel() {
    const int b  = blockIdx.z;
    const int i0 = blockIdx.y * TILE;
    const int j0 = blockIdx.x * TILE;

    __shared__ __align__(16) float sA2[CF][2 * TILE];   /* dup f1: 16KB */
    __shared__ __align__(16) float sB [CF][TILE];       /* f2: 8KB */
    __shared__ __align__(16) float sX1d[4][2 * TILE];   /* dup i-geom: 4KB */
    __shared__ __align__(16) float sJT[3][TILE];
    __shared__ __align__(16) float sJN[3][TILE];
    __shared__ __align__(16) float sbt[TILE], sbn[TILE];

    const int tid = threadIdx.x;

    /* cooperative tile loads, all float4 */
    {
#pragma unroll
        for (int k = 0; k < 2; k++) {                 /* sA2: 1024 float4 */
            int idx = tid + k * 512;
            int c = idx >> 6, q = idx & 63;
            ((float4*)sA2)[idx] = *(const float4*)&g_f1d[b][c][2 * i0 + q * 4];
        }
        {                                             /* sB: 512 float4 */
            int c = tid >> 5, q = tid & 31;
            ((float4*)sB)[tid] = *(const float4*)&g_f2n[b][c][j0 + q * 4];
        }
        if (tid < 256) {                              /* sX1d: 256 float4 */
            int r = tid >> 6, q = tid & 63;
            ((float4*)sX1d)[tid] = *(const float4*)&g_x1d[b][r][2 * i0 + q * 4];
        } else {                                      /* j-side geometry: 256 float4 */
            int t = tid - 256;
            if (t < 96) {
                int r = t >> 5, q = t & 31;
                ((float4*)sJT)[t] = *(const float4*)&g_xt[b][r][j0 + q * 4];
            } else if (t < 192) {
                int t2 = t - 96, r = t2 >> 5, q = t2 & 31;
                ((float4*)sJN)[t2] = *(const float4*)&g_xn[b][r][j0 + q * 4];
            } else if (t < 224) {
                ((float4*)sbt)[t - 192] = *(const float4*)&g_bts[b][j0 + (t - 192) * 4];
            } else {
                ((float4*)sbn)[t - 224] = *(const float4*)&g_bns[b][j0 + (t - 224) * 4];
            }
        }
    }
    __syncthreads();

    const int ty = tid >> 5;   /* warp id: 8 i rows (warp-uniform a-side) */
    const int tx = tid & 31;   /* lane: 4 j cols */
    const int iL = ty * 8;
    const int jL = tx * 4;

    /* ---- gramian: 8i x 4j, packed over j-pairs, zero-mov operands ---- */
    u64 acc[8][2];
#pragma unroll
    for (int ii = 0; ii < 8; ii++) { acc[ii][0] = 0ull; acc[ii][1] = 0ull; }

#pragma unroll
    for (int c = 0; c < CF; c++) {
        const float* arow = &sA2[c][ty * 16];
        u64 ad[8];
#pragma unroll
        for (int p = 0; p < 4; p++) {                 /* broadcast LDS.128 */
            ulonglong2 v = *(const ulonglong2*)&arow[p * 4];
            ad[2 * p] = v.x; ad[2 * p + 1] = v.y;
        }
        ulonglong2 bv = *(const ulonglong2*)&sB[c][jL];
#pragma unroll
        for (int ii = 0; ii < 8; ii++) {
            fma2(acc[ii][0], ad[ii], bv.x);
            fma2(acc[ii][1], ad[ii], bv.y);
        }
    }

    /* ---- RBF phase: j-side hoisted into registers as native u64 pairs -- */
    ulonglong2 T0 = *(const ulonglong2*)&sJT[0][jL];
    ulonglong2 T1 = *(const ulonglong2*)&sJT[1][jL];
    ulonglong2 T2 = *(const ulonglong2*)&sJT[2][jL];
    ulonglong2 N0 = *(const ulonglong2*)&sJN[0][jL];
    ulonglong2 N1 = *(const ulonglong2*)&sJN[1][jL];
    ulonglong2 N2 = *(const ulonglong2*)&sJN[2][jL];
    ulonglong2 BT = *(const ulonglong2*)&sbt[jL];
    ulonglong2 BN = *(const ulonglong2*)&sbn[jL];

    float part = 0.f;
#pragma unroll
    for (int ii = 0; ii < 8; ii++) {
        const int i2 = (iL + ii) * 2;
        u64 xd0 = *(const u64*)&sX1d[0][i2];   /* broadcast LDS.64, pre-dup'd */
        u64 xd1 = *(const u64*)&sX1d[1][i2];
        u64 xd2 = *(const u64*)&sX1d[2][i2];
        u64 asd = *(const u64*)&sX1d[3][i2];

        /* jp = 0 */
        {
            u64 st = add2(asd, BT.x);
            fma2(st, xd0, T0.x); fma2(st, xd1, T1.x); fma2(st, xd2, T2.x);
            u64 sn = add2(asd, BN.x);
            fma2(sn, xd0, N0.x); fma2(sn, xd1, N1.x); fma2(sn, xd2, N2.x);
            float2 stf = unpk(st), snf = unpk(sn), g = unpk(acc[ii][0]);
            part = fmaf(fexp2(stf.x) - fexp2(snf.x), g.x, part);
            part = fmaf(fexp2(stf.y) - fexp2(snf.y), g.y, part);
        }
        /* jp = 1 */
        {
            u64 st = add2(asd, BT.y);
            fma2(st, xd0, T0.y); fma2(st, xd1, T1.y); fma2(st, xd2, T2.y);
            u64 sn = add2(asd, BN.y);
            fma2(sn, xd0, N0.y); fma2(sn, xd1, N1.y); fma2(sn, xd2, N2.y);
            float2 stf = unpk(st), snf = unpk(sn), g = unpk(acc[ii][1]);
            part = fmaf(fexp2(stf.x) - fexp2(snf.x), g.x, part);
            part = fmaf(fexp2(stf.y) - fexp2(snf.y), g.y, part);
        }
    }

    /* ---- block reduce -> one double atomic ---- */
#pragma unroll
    for (int o = 16; o; o >>= 1) part += __shfl_down_sync(0xffffffffu, part, o);
    __shared__ float warpsum[16];
    if ((tid & 31) == 0) warpsum[tid >> 5] = part;
    __syncthreads();
    if (tid == 0) {
        float s = 0.f;
#pragma unroll
        for (int w = 0; w < 16; w++) s += warpsum[w];
        atomicAdd(&g_S[b], (double)s);
    }
}

/* ------------------------- finalize ------------------------------------ */
__global__ void fin_kernel(float* out) {
    double tot = 0.0;
    float fns = 0.f;
#pragma unroll
    for (int b = 0; b < BB; b++) {
        float s1 = 0.f, s2 = 0.f;
        for (int k = 0; k < PREPB; k++) {
            fns += g_part[b][k][0];
            s1  += g_part[b][k][1];
            s2  += g_part[b][k][2];
        }
        tot += g_S[b] / ((double)s1 * (double)s2);
    }
    float fl = (float)(-tot);
    out[0] = fl;
    out[1] = fl;
    out[2] = fns * 100.f;
}

/* ------------------------- launch --------------------------------------- */
extern "C" void kernel_launch(void* const* d_in, const int* in_sizes, int n_in,
                              void* d_out, int out_size) {
    const float* f1   = (const float*)d_in[0];
    const float* f2   = (const float*)d_in[1];
    const float* dp1  = (const float*)d_in[2];
    const float* dp2  = (const float*)d_in[3];
    const float* pose = (const float*)d_in[4];
    const float* yz1  = (const float*)d_in[7];
    float* out = (float*)d_out;

    prep_kernel<<<dim3(PREPB, BB), 256>>>(f1, f2, dp1, dp2, pose, yz1);
    pair_kernel<<<dim3(NT, NT, BB), 512>>>();
    fin_kernel<<<1, 1>>>(out);
}